// round 10
// baseline (speedup 1.0000x reference)
#include <cuda_runtime.h>
#include <cuda_fp16.h>
#include <math.h>
#include <stdint.h>

#define NTOK 4096      // BATCH * SEQ
#define SEQ  2048
#define DEMB 1024
#define DFF  4096
#define NH   16
#define DH   64

// ---------------------------------------------------------------------------
// Scratch (half activations for GEMM inputs; fp32 residual stream)
// ---------------------------------------------------------------------------
__device__ __half g_lnh [NTOK * DEMB];
__device__ __half g_qh  [NTOK * DEMB];
__device__ __half g_kh  [NTOK * DEMB];
__device__ __half g_vh  [NTOK * DEMB];
__device__ __half g_ctxh[NTOK * DEMB];
__device__ float  g_h   [NTOK * DEMB];
__device__ __half g_ffh [NTOK * DFF];
// half weights
__device__ __half g_wqh[DEMB * DEMB];
__device__ __half g_wkh[DEMB * DEMB];
__device__ __half g_wvh[DEMB * DEMB];
__device__ __half g_woh[DEMB * DEMB];
__device__ __half g_w1h[DFF * DEMB];
__device__ __half g_w2h[DEMB * DFF];

// ---------------------------------------------------------------------------
// Helpers
// ---------------------------------------------------------------------------
__device__ __forceinline__ float gelu_tanh(float u) {
    return 0.5f * u * (1.f + tanhf(0.7978845608028654f * (u + 0.044715f * u * u * u)));
}
__device__ __forceinline__ uint32_t f2tf(float f) {
    uint32_t u;
    asm("cvt.rna.tf32.f32 %0, %1;" : "=r"(u) : "f"(f));
    return u;
}
__device__ __forceinline__ uint32_t packh2(float lo, float hi) {
    __half2 h = __floats2half2_rn(lo, hi);
    return *reinterpret_cast<uint32_t*>(&h);
}
__device__ __forceinline__ void mma_tf32(float c[4],
    uint32_t a0, uint32_t a1, uint32_t a2, uint32_t a3, uint32_t b0, uint32_t b1)
{
    asm volatile(
        "mma.sync.aligned.m16n8k8.row.col.f32.tf32.tf32.f32 "
        "{%0,%1,%2,%3}, {%4,%5,%6,%7}, {%8,%9}, {%0,%1,%2,%3};\n"
        : "+f"(c[0]), "+f"(c[1]), "+f"(c[2]), "+f"(c[3])
        : "r"(a0), "r"(a1), "r"(a2), "r"(a3), "r"(b0), "r"(b1));
}
__device__ __forceinline__ void mma_f16(float c[4],
    uint32_t a0, uint32_t a1, uint32_t a2, uint32_t a3, uint32_t b0, uint32_t b1)
{
    asm volatile(
        "mma.sync.aligned.m16n8k16.row.col.f32.f16.f16.f32 "
        "{%0,%1,%2,%3}, {%4,%5,%6,%7}, {%8,%9}, {%0,%1,%2,%3};\n"
        : "+f"(c[0]), "+f"(c[1]), "+f"(c[2]), "+f"(c[3])
        : "r"(a0), "r"(a1), "r"(a2), "r"(a3), "r"(b0), "r"(b1));
}
__device__ __forceinline__ void ldsm4(uint32_t r[4], uint32_t addr) {
    asm volatile("ldmatrix.sync.aligned.m8n8.x4.shared.b16 {%0,%1,%2,%3}, [%4];"
        : "=r"(r[0]), "=r"(r[1]), "=r"(r[2]), "=r"(r[3]) : "r"(addr));
}
__device__ __forceinline__ void cpasync16(uint32_t dst, const void* src) {
    asm volatile("cp.async.ca.shared.global [%0], [%1], 16;\n" :: "r"(dst), "l"(src));
}
__device__ __forceinline__ void u8from(uint32_t* w, uint4 a, uint4 b) {
    w[0]=a.x; w[1]=a.y; w[2]=a.z; w[3]=a.w;
    w[4]=b.x; w[5]=b.y; w[6]=b.z; w[7]=b.w;
}

// ---------------------------------------------------------------------------
// Weight conversion fp32 -> half (grid-stride, float4 -> half4)
// ---------------------------------------------------------------------------
__global__ void __launch_bounds__(256) cvt_w(const float* __restrict__ src,
                                             __half* __restrict__ dst, int n4)
{
    for (int i = blockIdx.x * 256 + threadIdx.x; i < n4; i += gridDim.x * 256) {
        float4 v = ((const float4*)src)[i];
        uint2 o;
        o.x = packh2(v.x, v.y);
        o.y = packh2(v.z, v.w);
        ((uint2*)dst)[i] = o;
    }
}

// ---------------------------------------------------------------------------
// LayerNorm (fp32 in, half out)
// ---------------------------------------------------------------------------
__global__ void __launch_bounds__(256) ln_kernel(
    const float* __restrict__ x, const float* __restrict__ sc,
    const float* __restrict__ sh, __half* __restrict__ y)
{
    int row = blockIdx.x;
    const float* xr = x + (size_t)row * DEMB;
    __half* yr = y + (size_t)row * DEMB;

    float sum = 0.f, sq = 0.f;
    for (int i = threadIdx.x; i < DEMB; i += 256) {
        float v = xr[i];
        sum += v; sq += v * v;
    }
    for (int o = 16; o > 0; o >>= 1) {
        sum += __shfl_down_sync(0xffffffffu, sum, o);
        sq  += __shfl_down_sync(0xffffffffu, sq,  o);
    }
    __shared__ float rs[8], rq[8];
    int wid = threadIdx.x >> 5, lane = threadIdx.x & 31;
    if (lane == 0) { rs[wid] = sum; rq[wid] = sq; }
    __syncthreads();
    __shared__ float s_mean, s_inv;
    if (wid == 0) {
        float a = (lane < 8) ? rs[lane] : 0.f;
        float b = (lane < 8) ? rq[lane] : 0.f;
        for (int o = 4; o > 0; o >>= 1) {
            a += __shfl_down_sync(0xffffffffu, a, o);
            b += __shfl_down_sync(0xffffffffu, b, o);
        }
        if (lane == 0) {
            float mean = a * (1.f / DEMB);
            float var  = b * (1.f / DEMB) - mean * mean;
            s_mean = mean;
            s_inv  = rsqrtf(var + 1e-6f);
        }
    }
    __syncthreads();
    float mean = s_mean, inv = s_inv;
    for (int i = threadIdx.x; i < DEMB; i += 256) {
        yr[i] = __float2half(sc[i] * (xr[i] - mean) * inv + sh[i]);
    }
}

// ---------------------------------------------------------------------------
// HGEMM: C[M,N] = A[M,K]h @ W[N,K]h^T (+bias)(+res fp32)(GELU), fp32 accum.
// 128x128 tile, BK=32, 4-stage cp.async pipeline, ldmatrix fragments with
// XOR-swizzled smem (chunk_phys = c ^ ((r>>1)&3)) -> conflict-free LDSM.
// ---------------------------------------------------------------------------
#define NSTAGE 4
#define STAGE_BYTES (128 * 64)   // 128 rows x 32 halves

template<int BIAS, int GELU, int RES, int OUTH>
__global__ void __launch_bounds__(256) gemm_h(
    const __half* __restrict__ A, const __half* __restrict__ W,
    const float* __restrict__ bias, const float* __restrict__ res,
    void* __restrict__ Cout, int M, int N, int K)
{
    extern __shared__ __align__(16) uint8_t smem[];
    uint32_t sA = (uint32_t)__cvta_generic_to_shared(smem);
    uint32_t sB = sA + NSTAGE * STAGE_BYTES;

    int tid = threadIdx.x;
    int m0 = blockIdx.y * 128, n0 = blockIdx.x * 128;

    // --- cp.async mapping: thread -> (row, 2 chunks of 16B) ---
    int r  = tid >> 1;           // 0..127
    int c2 = (tid & 1) * 2;      // chunk 0 or 2
    const __half* Ag = A + (size_t)(m0 + r) * K + c2 * 8;
    const __half* Wg = W + (size_t)(n0 + r) * K + c2 * 8;
    int swr = (r >> 1) & 3;
    uint32_t dA0 = sA + (r * 4 + ((c2    ) ^ swr)) * 16;
    uint32_t dA1 = sA + (r * 4 + ((c2 + 1) ^ swr)) * 16;
    uint32_t dB0 = sB + (r * 4 + ((c2    ) ^ swr)) * 16;
    uint32_t dB1 = sB + (r * 4 + ((c2 + 1) ^ swr)) * 16;

    // --- fragment (ldmatrix) lane mapping ---
    int warp = tid >> 5, lane = tid & 31;
    int wm = (warp >> 2) * 64;
    int wn = (warp & 3) * 32;
    int g = lane >> 2, t = lane & 3;

    int arow = (lane & 7) + 8 * ((lane >> 3) & 1);   // 0..15
    int acb  = lane >> 4;                            // chunk bit
    uint32_t aBase[4]; int aSw[4];
#pragma unroll
    for (int mt = 0; mt < 4; mt++) {
        int rr = wm + mt * 16 + arow;
        aBase[mt] = sA + rr * 64;
        aSw[mt] = (rr >> 1) & 3;
    }
    int boct = lane >> 4;            // nt offset within pair
    int bcb  = (lane >> 3) & 1;      // chunk bit
    uint32_t bBase[2]; int bSw[2];
#pragma unroll
    for (int p = 0; p < 2; p++) {
        int rr = wn + (2 * p + boct) * 8 + (lane & 7);
        bBase[p] = sB + rr * 64;
        bSw[p] = (rr >> 1) & 3;
    }

    float acc[4][4][4];
#pragma unroll
    for (int i = 0; i < 4; i++)
#pragma unroll
        for (int j = 0; j < 4; j++)
#pragma unroll
            for (int c = 0; c < 4; c++) acc[i][j][c] = 0.f;

    int KT = K >> 5;   // K/32

    // prologue: fill NSTAGE-1 stages
#pragma unroll
    for (int s = 0; s < NSTAGE - 1; s++) {
        uint32_t so = s * STAGE_BYTES;
        int k0 = s * 32;
        cpasync16(dA0 + so, Ag + k0);
        cpasync16(dA1 + so, Ag + k0 + 8);
        cpasync16(dB0 + so, Wg + k0);
        cpasync16(dB1 + so, Wg + k0 + 8);
        asm volatile("cp.async.commit_group;\n");
    }

    for (int it = 0; it < KT; it++) {
        asm volatile("cp.async.wait_group %0;\n" :: "n"(NSTAGE - 2));
        __syncthreads();

        uint32_t so = (it % NSTAGE) * STAGE_BYTES;
#pragma unroll
        for (int s = 0; s < 2; s++) {
            uint32_t a[4][4], b[2][4];
#pragma unroll
            for (int mt = 0; mt < 4; mt++)
                ldsm4(a[mt], aBase[mt] + so + ((((2 * s + acb)) ^ aSw[mt]) << 4));
#pragma unroll
            for (int p = 0; p < 2; p++)
                ldsm4(b[p], bBase[p] + so + ((((2 * s + bcb)) ^ bSw[p]) << 4));
#pragma unroll
            for (int mt = 0; mt < 4; mt++) {
#pragma unroll
                for (int nt = 0; nt < 4; nt++) {
                    int p = nt >> 1, q = nt & 1;
                    mma_f16(acc[mt][nt], a[mt][0], a[mt][1], a[mt][2], a[mt][3],
                            b[p][2 * q], b[p][2 * q + 1]);
                }
            }
        }

        int nx = it + NSTAGE - 1;
        if (nx < KT) {
            uint32_t sn = (nx % NSTAGE) * STAGE_BYTES;
            int k0 = nx * 32;
            cpasync16(dA0 + sn, Ag + k0);
            cpasync16(dA1 + sn, Ag + k0 + 8);
            cpasync16(dB0 + sn, Wg + k0);
            cpasync16(dB1 + sn, Wg + k0 + 8);
        }
        asm volatile("cp.async.commit_group;\n");
    }

    // epilogue
#pragma unroll
    for (int mt = 0; mt < 4; mt++) {
        int rr = m0 + wm + mt * 16 + g;
#pragma unroll
        for (int nt = 0; nt < 4; nt++) {
            int cc = n0 + wn + nt * 8 + 2 * t;
            float v0 = acc[mt][nt][0], v1 = acc[mt][nt][1];
            float v2 = acc[mt][nt][2], v3 = acc[mt][nt][3];
            if (BIAS) {
                float b0 = bias[cc], b1 = bias[cc + 1];
                v0 += b0; v1 += b1; v2 += b0; v3 += b1;
            }
            if (RES) {
                const float* rp0 = res + (size_t)rr * N + cc;
                const float* rp1 = res + (size_t)(rr + 8) * N + cc;
                v0 += rp0[0]; v1 += rp0[1];
                v2 += rp1[0]; v3 += rp1[1];
            }
            if (GELU) {
                v0 = gelu_tanh(v0); v1 = gelu_tanh(v1);
                v2 = gelu_tanh(v2); v3 = gelu_tanh(v3);
            }
            if (OUTH) {
                __half* C = (__half*)Cout;
                *(uint32_t*)(C + (size_t)rr * N + cc)       = packh2(v0, v1);
                *(uint32_t*)(C + (size_t)(rr + 8) * N + cc) = packh2(v2, v3);
            } else {
                float* C = (float*)Cout;
                *(float2*)(C + (size_t)rr * N + cc)       = make_float2(v0, v1);
                *(float2*)(C + (size_t)(rr + 8) * N + cc) = make_float2(v2, v3);
            }
        }
    }
}

// ---------------------------------------------------------------------------
// Tensor-core causal flash attention (tf32 compute, half I/O)
// ---------------------------------------------------------------------------
#define KST 68
#define VST 68
#define PST 68

extern __shared__ uint32_t s_attn[];

__global__ void __launch_bounds__(256) attn_tc_kernel()
{
    uint32_t* sK  = s_attn;
    uint32_t* sVT = s_attn + 64 * KST;
    uint32_t* sP  = s_attn + 64 * KST + 64 * VST;

    int tid = threadIdx.x;
    int bh = blockIdx.y;
    int b = bh >> 4, h = bh & 15;
    int qi = (int)(gridDim.x - 1) - (int)blockIdx.x;
    int q0 = qi * 128;

    int warp = tid >> 5, lane = tid & 31;
    int wm = warp * 16;
    int g = lane >> 2, t = lane & 3;

    int r0 = q0 + wm + g;
    int r1 = r0 + 8;
    int tok0 = b * SEQ + r0;

    const __half* Qb  = g_qh + (size_t)tok0 * DEMB + h * 64;
    const __half* Qb8 = Qb + (size_t)8 * DEMB;
    uint32_t qf[8][4];
#pragma unroll
    for (int kc = 0; kc < 8; kc++) {
        qf[kc][0] = f2tf(0.125f * __half2float(Qb [8 * kc + t]));
        qf[kc][1] = f2tf(0.125f * __half2float(Qb8[8 * kc + t]));
        qf[kc][2] = f2tf(0.125f * __half2float(Qb [8 * kc + t + 4]));
        qf[kc][3] = f2tf(0.125f * __half2float(Qb8[8 * kc + t + 4]));
    }

    float of[8][4];
#pragma unroll
    for (int j = 0; j < 8; j++)
#pragma unroll
        for (int c = 0; c < 4; c++) of[j][c] = 0.f;
    float m0 = -1e30f, m1 = -1e30f, l0 = 0.f, l1 = 0.f;

    int krow = tid >> 2;
    int kcg  = tid & 3;

    int ktmax = (q0 >> 6) + 1;
    for (int kt = 0; kt <= ktmax; kt++) {
        __syncthreads();
        {
            int ktok = b * SEQ + kt * 64 + krow;
            const uint4* Ksrc = (const uint4*)(g_kh + (size_t)ktok * DEMB + h * 64);
            const uint4* Vsrc = (const uint4*)(g_vh + (size_t)ktok * DEMB + h * 64);
            int pk = 8 * (krow & 7) + (krow >> 3);
#pragma unroll
            for (int j = 0; j < 2; j++) {
                int u4 = kcg * 2 + j;          // 0..7, 8 halves each
                int d0 = u4 * 8;
                uint4 kraw = Ksrc[u4];
                const __half2* kp = (const __half2*)&kraw;
                uint32_t* kr = sK + krow * KST + u4;
#pragma unroll
                for (int i = 0; i < 4; i++) {
                    float2 f = __half22float2(kp[i]);
                    kr[8 * (2 * i)]     = f2tf(f.x);
                    kr[8 * (2 * i + 1)] = f2tf(f.y);
                }
                uint4 vraw = Vsrc[u4];
                const __half2* vp = (const __half2*)&vraw;
#pragma unroll
                for (int i = 0; i < 4; i++) {
                    float2 f = __half22float2(vp[i]);
                    sVT[(d0 + 2 * i) * VST + pk]     = f2tf(f.x);
                    sVT[(d0 + 2 * i + 1) * VST + pk] = f2tf(f.y);
                }
            }
        }
        __syncthreads();

        float sf[8][4];
#pragma unroll
        for (int jn = 0; jn < 8; jn++) {
            const uint32_t* kr = sK + (8 * jn + g) * KST;
            uint4 bl0 = *(const uint4*)(kr + 8 * t);
            uint4 bl1 = *(const uint4*)(kr + 8 * t + 4);
            uint4 bh0 = *(const uint4*)(kr + 8 * (t + 4));
            uint4 bh1 = *(const uint4*)(kr + 8 * (t + 4) + 4);
            uint32_t b0w[8], b1w[8];
            u8from(b0w, bl0, bl1);
            u8from(b1w, bh0, bh1);
            float c[4] = {0.f, 0.f, 0.f, 0.f};
#pragma unroll
            for (int kc = 0; kc < 8; kc++)
                mma_tf32(c, qf[kc][0], qf[kc][1], qf[kc][2], qf[kc][3],
                         b0w[kc], b1w[kc]);
            sf[jn][0] = c[0]; sf[jn][1] = c[1];
            sf[jn][2] = c[2]; sf[jn][3] = c[3];
        }

        if (kt * 64 + 63 > q0 + wm) {
#pragma unroll
            for (int jn = 0; jn < 8; jn++) {
                int col = kt * 64 + 8 * jn + 2 * t;
                if (col     > r0) sf[jn][0] = -1e30f;
                if (col + 1 > r0) sf[jn][1] = -1e30f;
                if (col     > r1) sf[jn][2] = -1e30f;
                if (col + 1 > r1) sf[jn][3] = -1e30f;
            }
        }

        float rx0 = -1e30f, rx1 = -1e30f;
#pragma unroll
        for (int jn = 0; jn < 8; jn++) {
            rx0 = fmaxf(rx0, fmaxf(sf[jn][0], sf[jn][1]));
            rx1 = fmaxf(rx1, fmaxf(sf[jn][2], sf[jn][3]));
        }
        rx0 = fmaxf(rx0, __shfl_xor_sync(0xffffffffu, rx0, 1));
        rx0 = fmaxf(rx0, __shfl_xor_sync(0xffffffffu, rx0, 2));
        rx1 = fmaxf(rx1, __shfl_xor_sync(0xffffffffu, rx1, 1));
        rx1 = fmaxf(rx1, __shfl_xor_sync(0xffffffffu, rx1, 2));

        float mn0 = fmaxf(m0, rx0), mn1 = fmaxf(m1, rx1);
        float cor0 = __expf(m0 - mn0), cor1 = __expf(m1 - mn1);
        m0 = mn0; m1 = mn1;
        l0 *= cor0; l1 *= cor1;
#pragma unroll
        for (int j = 0; j < 8; j++) {
            of[j][0] *= cor0; of[j][1] *= cor0;
            of[j][2] *= cor1; of[j][3] *= cor1;
        }

        uint32_t* pw  = sP + (wm + g) * PST;
        uint32_t* pw8 = sP + (wm + 8 + g) * PST;
#pragma unroll
        for (int jn = 0; jn < 8; jn++) {
            float p0 = __expf(sf[jn][0] - m0);
            float p1 = __expf(sf[jn][1] - m0);
            float p2 = __expf(sf[jn][2] - m1);
            float p3 = __expf(sf[jn][3] - m1);
            l0 += p0 + p1; l1 += p2 + p3;
            pw [16 * t + jn]     = f2tf(p0);
            pw [16 * t + 8 + jn] = f2tf(p1);
            pw8[16 * t + jn]     = f2tf(p2);
            pw8[16 * t + 8 + jn] = f2tf(p3);
        }
        __syncwarp();

        const uint32_t* p0r = sP + (wm + g) * PST;
        const uint32_t* p8r = sP + (wm + 8 + g) * PST;
        uint4 A0a = *(const uint4*)(p0r + 8 * t);
        uint4 A0b = *(const uint4*)(p0r + 8 * t + 4);
        uint4 A2a = *(const uint4*)(p0r + 8 * (t + 4));
        uint4 A2b = *(const uint4*)(p0r + 8 * (t + 4) + 4);
        uint4 A1a = *(const uint4*)(p8r + 8 * t);
        uint4 A1b = *(const uint4*)(p8r + 8 * t + 4);
        uint4 A3a = *(const uint4*)(p8r + 8 * (t + 4));
        uint4 A3b = *(const uint4*)(p8r + 8 * (t + 4) + 4);
        uint32_t a0w[8], a1w[8], a2w[8], a3w[8];
        u8from(a0w, A0a, A0b);
        u8from(a1w, A1a, A1b);
        u8from(a2w, A2a, A2b);
        u8from(a3w, A3a, A3b);

#pragma unroll
        for (int jd = 0; jd < 8; jd++) {
            const uint32_t* vr = sVT + (8 * jd + g) * VST;
            uint4 vb0a = *(const uint4*)(vr + 8 * t);
            uint4 vb0b = *(const uint4*)(vr + 8 * t + 4);
            uint4 vb1a = *(const uint4*)(vr + 8 * (t + 4));
            uint4 vb1b = *(const uint4*)(vr + 8 * (t + 4) + 4);
            uint32_t b0w[8], b1w[8];
            u8from(b0w, vb0a, vb0b);
            u8from(b1w, vb1a, vb1b);
#pragma unroll
            for (int kc = 0; kc < 8; kc++)
                mma_tf32(of[jd], a0w[kc], a1w[kc], a2w[kc], a3w[kc],
                         b0w[kc], b1w[kc]);
        }
    }

    l0 += __shfl_xor_sync(0xffffffffu, l0, 1);
    l0 += __shfl_xor_sync(0xffffffffu, l0, 2);
    l1 += __shfl_xor_sync(0xffffffffu, l1, 1);
    l1 += __shfl_xor_sync(0xffffffffu, l1, 2);
    float i0 = 1.f / l0, i1 = 1.f / l1;

    __half* C0 = g_ctxh + (size_t)tok0 * DEMB + h * 64;
    __half* C1 = C0 + (size_t)8 * DEMB;
#pragma unroll
    for (int jd = 0; jd < 8; jd++) {
        *(uint32_t*)(C0 + 8 * jd + 2 * t) = packh2(of[jd][0] * i0, of[jd][1] * i0);
        *(uint32_t*)(C1 + 8 * jd + 2 * t) = packh2(of[jd][2] * i1, of[jd][3] * i1);
    }
}

#define ATTN_SMEM ((64 * KST + 64 * VST + 128 * PST) * 4)
#define GEMM_SMEM (2 * NSTAGE * STAGE_BYTES)

// ---------------------------------------------------------------------------
// Launch
// ---------------------------------------------------------------------------
extern "C" void kernel_launch(void* const* d_in, const int* in_sizes, int n_in,
                              void* d_out, int out_size)
{
    const float* x     = (const float*)d_in[0];
    const float* wq    = (const float*)d_in[1];
    const float* wk    = (const float*)d_in[2];
    const float* wv    = (const float*)d_in[3];
    const float* wo    = (const float*)d_in[4];
    const float* bo    = (const float*)d_in[5];
    const float* w1    = (const float*)d_in[6];
    const float* b1    = (const float*)d_in[7];
    const float* w2    = (const float*)d_in[8];
    const float* b2    = (const float*)d_in[9];
    const float* ln1_s = (const float*)d_in[10];
    const float* ln1_b = (const float*)d_in[11];
    const float* ln2_s = (const float*)d_in[12];
    const float* ln2_b = (const float*)d_in[13];
    float* out = (float*)d_out;

    __half *p_lnh, *p_qh, *p_kh, *p_vh, *p_ctxh, *p_ffh;
    __half *p_wqh, *p_wkh, *p_wvh, *p_woh, *p_w1h, *p_w2h;
    float *p_h;
    cudaGetSymbolAddress((void**)&p_lnh,  g_lnh);
    cudaGetSymbolAddress((void**)&p_qh,   g_qh);
    cudaGetSymbolAddress((void**)&p_kh,   g_kh);
    cudaGetSymbolAddress((void**)&p_vh,   g_vh);
    cudaGetSymbolAddress((void**)&p_ctxh, g_ctxh);
    cudaGetSymbolAddress((void**)&p_ffh,  g_ffh);
    cudaGetSymbolAddress((void**)&p_h,    g_h);
    cudaGetSymbolAddress((void**)&p_wqh,  g_wqh);
    cudaGetSymbolAddress((void**)&p_wkh,  g_wkh);
    cudaGetSymbolAddress((void**)&p_wvh,  g_wvh);
    cudaGetSymbolAddress((void**)&p_woh,  g_woh);
    cudaGetSymbolAddress((void**)&p_w1h,  g_w1h);
    cudaGetSymbolAddress((void**)&p_w2h,  g_w2h);

    cudaFuncSetAttribute(attn_tc_kernel,
        cudaFuncAttributeMaxDynamicSharedMemorySize, ATTN_SMEM);
    cudaFuncSetAttribute(gemm_h<0,0,0,1>,
        cudaFuncAttributeMaxDynamicSharedMemorySize, GEMM_SMEM);
    cudaFuncSetAttribute(gemm_h<1,0,1,0>,
        cudaFuncAttributeMaxDynamicSharedMemorySize, GEMM_SMEM);
    cudaFuncSetAttribute(gemm_h<1,1,0,1>,
        cudaFuncAttributeMaxDynamicSharedMemorySize, GEMM_SMEM);

    // weight conversion (runs every launch; deterministic)
    cvt_w<<<256, 256>>>(wq, p_wqh, DEMB * DEMB / 4);
    cvt_w<<<256, 256>>>(wk, p_wkh, DEMB * DEMB / 4);
    cvt_w<<<256, 256>>>(wv, p_wvh, DEMB * DEMB / 4);
    cvt_w<<<256, 256>>>(wo, p_woh, DEMB * DEMB / 4);
    cvt_w<<<512, 256>>>(w1, p_w1h, DFF * DEMB / 4);
    cvt_w<<<512, 256>>>(w2, p_w2h, DEMB * DFF / 4);

    dim3 gD(DEMB / 128, NTOK / 128);
    dim3 gF(DFF  / 128, NTOK / 128);

    ln_kernel<<<NTOK, 256>>>(x, ln1_s, ln1_b, p_lnh);
    gemm_h<0,0,0,1><<<gD, 256, GEMM_SMEM>>>(p_lnh, p_wqh, nullptr, nullptr, p_qh, NTOK, DEMB, DEMB);
    gemm_h<0,0,0,1><<<gD, 256, GEMM_SMEM>>>(p_lnh, p_wkh, nullptr, nullptr, p_kh, NTOK, DEMB, DEMB);
    gemm_h<0,0,0,1><<<gD, 256, GEMM_SMEM>>>(p_lnh, p_wvh, nullptr, nullptr, p_vh, NTOK, DEMB, DEMB);
    attn_tc_kernel<<<dim3(SEQ / 128, 2 * NH), 256, ATTN_SMEM>>>();
    gemm_h<1,0,1,0><<<gD, 256, GEMM_SMEM>>>(p_ctxh, p_woh, bo, x, p_h, NTOK, DEMB, DEMB);
    ln_kernel<<<NTOK, 256>>>(p_h, ln2_s, ln2_b, p_lnh);
    gemm_h<1,1,0,1><<<gF, 256, GEMM_SMEM>>>(p_lnh, p_w1h, b1, nullptr, p_ffh, NTOK, DFF, DEMB);
    gemm_h<1,0,1,0><<<gD, 256, GEMM_SMEM>>>(p_ffh, p_w2h, b2, p_h, out, NTOK, DEMB, DFF);
}

// round 11
// speedup vs baseline: 1.0026x; 1.0026x over previous
#include <cuda_runtime.h>
#include <cuda_fp16.h>
#include <math.h>
#include <stdint.h>

#define NTOK 4096      // BATCH * SEQ
#define SEQ  2048
#define DEMB 1024
#define DFF  4096
#define NH   16
#define DH   64

// ---------------------------------------------------------------------------
// Scratch (half activations for GEMM inputs; fp32 residual stream)
// ---------------------------------------------------------------------------
__device__ __half g_lnh [NTOK * DEMB];
__device__ __half g_qh  [NTOK * DEMB];
__device__ __half g_kh  [NTOK * DEMB];
__device__ __half g_vh  [NTOK * DEMB];
__device__ __half g_ctxh[NTOK * DEMB];
__device__ float  g_h   [NTOK * DEMB];
__device__ __half g_ffh [NTOK * DFF];
// half weights
__device__ __half g_wqh[DEMB * DEMB];
__device__ __half g_wkh[DEMB * DEMB];
__device__ __half g_wvh[DEMB * DEMB];
__device__ __half g_woh[DEMB * DEMB];
__device__ __half g_w1h[DFF * DEMB];
__device__ __half g_w2h[DEMB * DFF];

// ---------------------------------------------------------------------------
// Helpers
// ---------------------------------------------------------------------------
__device__ __forceinline__ float gelu_tanh(float u) {
    return 0.5f * u * (1.f + tanhf(0.7978845608028654f * (u + 0.044715f * u * u * u)));
}
__device__ __forceinline__ uint32_t f2tf(float f) {
    uint32_t u;
    asm("cvt.rna.tf32.f32 %0, %1;" : "=r"(u) : "f"(f));
    return u;
}
__device__ __forceinline__ uint32_t packh2(float lo, float hi) {
    __half2 h = __floats2half2_rn(lo, hi);
    return *reinterpret_cast<uint32_t*>(&h);
}
__device__ __forceinline__ void mma_tf32(float c[4],
    uint32_t a0, uint32_t a1, uint32_t a2, uint32_t a3, uint32_t b0, uint32_t b1)
{
    asm volatile(
        "mma.sync.aligned.m16n8k8.row.col.f32.tf32.tf32.f32 "
        "{%0,%1,%2,%3}, {%4,%5,%6,%7}, {%8,%9}, {%0,%1,%2,%3};\n"
        : "+f"(c[0]), "+f"(c[1]), "+f"(c[2]), "+f"(c[3])
        : "r"(a0), "r"(a1), "r"(a2), "r"(a3), "r"(b0), "r"(b1));
}
__device__ __forceinline__ void mma_f16(float c[4],
    uint32_t a0, uint32_t a1, uint32_t a2, uint32_t a3, uint32_t b0, uint32_t b1)
{
    asm volatile(
        "mma.sync.aligned.m16n8k16.row.col.f32.f16.f16.f32 "
        "{%0,%1,%2,%3}, {%4,%5,%6,%7}, {%8,%9}, {%0,%1,%2,%3};\n"
        : "+f"(c[0]), "+f"(c[1]), "+f"(c[2]), "+f"(c[3])
        : "r"(a0), "r"(a1), "r"(a2), "r"(a3), "r"(b0), "r"(b1));
}
__device__ __forceinline__ void ldsm4(uint32_t r[4], uint32_t addr) {
    asm volatile("ldmatrix.sync.aligned.m8n8.x4.shared.b16 {%0,%1,%2,%3}, [%4];"
        : "=r"(r[0]), "=r"(r[1]), "=r"(r[2]), "=r"(r[3]) : "r"(addr));
}
__device__ __forceinline__ void cpasync16(uint32_t dst, const void* src) {
    asm volatile("cp.async.ca.shared.global [%0], [%1], 16;\n" :: "r"(dst), "l"(src));
}
__device__ __forceinline__ void u8from(uint32_t* w, uint4 a, uint4 b) {
    w[0]=a.x; w[1]=a.y; w[2]=a.z; w[3]=a.w;
    w[4]=b.x; w[5]=b.y; w[6]=b.z; w[7]=b.w;
}

// ---------------------------------------------------------------------------
// Weight conversion fp32 -> half (grid-stride, float4 -> half4)
// ---------------------------------------------------------------------------
__global__ void __launch_bounds__(256) cvt_w(const float* __restrict__ src,
                                             __half* __restrict__ dst, int n4)
{
    for (int i = blockIdx.x * 256 + threadIdx.x; i < n4; i += gridDim.x * 256) {
        float4 v = ((const float4*)src)[i];
        uint2 o;
        o.x = packh2(v.x, v.y);
        o.y = packh2(v.z, v.w);
        ((uint2*)dst)[i] = o;
    }
}

// ---------------------------------------------------------------------------
// LayerNorm (fp32 in, half out)
// ---------------------------------------------------------------------------
__global__ void __launch_bounds__(256) ln_kernel(
    const float* __restrict__ x, const float* __restrict__ sc,
    const float* __restrict__ sh, __half* __restrict__ y)
{
    int row = blockIdx.x;
    const float* xr = x + (size_t)row * DEMB;
    __half* yr = y + (size_t)row * DEMB;

    float sum = 0.f, sq = 0.f;
    for (int i = threadIdx.x; i < DEMB; i += 256) {
        float v = xr[i];
        sum += v; sq += v * v;
    }
    for (int o = 16; o > 0; o >>= 1) {
        sum += __shfl_down_sync(0xffffffffu, sum, o);
        sq  += __shfl_down_sync(0xffffffffu, sq,  o);
    }
    __shared__ float rs[8], rq[8];
    int wid = threadIdx.x >> 5, lane = threadIdx.x & 31;
    if (lane == 0) { rs[wid] = sum; rq[wid] = sq; }
    __syncthreads();
    __shared__ float s_mean, s_inv;
    if (wid == 0) {
        float a = (lane < 8) ? rs[lane] : 0.f;
        float b = (lane < 8) ? rq[lane] : 0.f;
        for (int o = 4; o > 0; o >>= 1) {
            a += __shfl_down_sync(0xffffffffu, a, o);
            b += __shfl_down_sync(0xffffffffu, b, o);
        }
        if (lane == 0) {
            float mean = a * (1.f / DEMB);
            float var  = b * (1.f / DEMB) - mean * mean;
            s_mean = mean;
            s_inv  = rsqrtf(var + 1e-6f);
        }
    }
    __syncthreads();
    float mean = s_mean, inv = s_inv;
    for (int i = threadIdx.x; i < DEMB; i += 256) {
        yr[i] = __float2half(sc[i] * (xr[i] - mean) * inv + sh[i]);
    }
}

// ---------------------------------------------------------------------------
// HGEMM: C[M,N] = A[M,K]h @ W[N,K]h^T (+bias)(+res fp32)(GELU), fp32 accum.
// 128x128 tile, BK=32, 4-stage cp.async pipeline, ldmatrix fragments with
// XOR-swizzled smem (chunk_phys = c ^ ((r>>1)&3)) -> conflict-free LDSM.
// ---------------------------------------------------------------------------
#define NSTAGE 4
#define STAGE_BYTES (128 * 64)   // 128 rows x 32 halves

template<int BIAS, int GELU, int RES, int OUTH>
__global__ void __launch_bounds__(256) gemm_h(
    const __half* __restrict__ A, const __half* __restrict__ W,
    const float* __restrict__ bias, const float* __restrict__ res,
    void* __restrict__ Cout, int M, int N, int K)
{
    extern __shared__ __align__(16) uint8_t smem[];
    uint32_t sA = (uint32_t)__cvta_generic_to_shared(smem);
    uint32_t sB = sA + NSTAGE * STAGE_BYTES;

    int tid = threadIdx.x;
    int m0 = blockIdx.y * 128, n0 = blockIdx.x * 128;

    // --- cp.async mapping: thread -> (row, 2 chunks of 16B) ---
    int r  = tid >> 1;           // 0..127
    int c2 = (tid & 1) * 2;      // chunk 0 or 2
    const __half* Ag = A + (size_t)(m0 + r) * K + c2 * 8;
    const __half* Wg = W + (size_t)(n0 + r) * K + c2 * 8;
    int swr = (r >> 1) & 3;
    uint32_t dA0 = sA + (r * 4 + ((c2    ) ^ swr)) * 16;
    uint32_t dA1 = sA + (r * 4 + ((c2 + 1) ^ swr)) * 16;
    uint32_t dB0 = sB + (r * 4 + ((c2    ) ^ swr)) * 16;
    uint32_t dB1 = sB + (r * 4 + ((c2 + 1) ^ swr)) * 16;

    // --- fragment (ldmatrix) lane mapping ---
    int warp = tid >> 5, lane = tid & 31;
    int wm = (warp >> 2) * 64;
    int wn = (warp & 3) * 32;
    int g = lane >> 2, t = lane & 3;

    int arow = (lane & 7) + 8 * ((lane >> 3) & 1);   // 0..15
    int acb  = lane >> 4;                            // chunk bit
    uint32_t aBase[4]; int aSw[4];
#pragma unroll
    for (int mt = 0; mt < 4; mt++) {
        int rr = wm + mt * 16 + arow;
        aBase[mt] = sA + rr * 64;
        aSw[mt] = (rr >> 1) & 3;
    }
    int boct = lane >> 4;            // nt offset within pair
    int bcb  = (lane >> 3) & 1;      // chunk bit
    uint32_t bBase[2]; int bSw[2];
#pragma unroll
    for (int p = 0; p < 2; p++) {
        int rr = wn + (2 * p + boct) * 8 + (lane & 7);
        bBase[p] = sB + rr * 64;
        bSw[p] = (rr >> 1) & 3;
    }

    float acc[4][4][4];
#pragma unroll
    for (int i = 0; i < 4; i++)
#pragma unroll
        for (int j = 0; j < 4; j++)
#pragma unroll
            for (int c = 0; c < 4; c++) acc[i][j][c] = 0.f;

    int KT = K >> 5;   // K/32

    // prologue: fill NSTAGE-1 stages
#pragma unroll
    for (int s = 0; s < NSTAGE - 1; s++) {
        uint32_t so = s * STAGE_BYTES;
        int k0 = s * 32;
        cpasync16(dA0 + so, Ag + k0);
        cpasync16(dA1 + so, Ag + k0 + 8);
        cpasync16(dB0 + so, Wg + k0);
        cpasync16(dB1 + so, Wg + k0 + 8);
        asm volatile("cp.async.commit_group;\n");
    }

    for (int it = 0; it < KT; it++) {
        asm volatile("cp.async.wait_group %0;\n" :: "n"(NSTAGE - 2));
        __syncthreads();

        uint32_t so = (it % NSTAGE) * STAGE_BYTES;
#pragma unroll
        for (int s = 0; s < 2; s++) {
            uint32_t a[4][4], b[2][4];
#pragma unroll
            for (int mt = 0; mt < 4; mt++)
                ldsm4(a[mt], aBase[mt] + so + ((((2 * s + acb)) ^ aSw[mt]) << 4));
#pragma unroll
            for (int p = 0; p < 2; p++)
                ldsm4(b[p], bBase[p] + so + ((((2 * s + bcb)) ^ bSw[p]) << 4));
#pragma unroll
            for (int mt = 0; mt < 4; mt++) {
#pragma unroll
                for (int nt = 0; nt < 4; nt++) {
                    int p = nt >> 1, q = nt & 1;
                    mma_f16(acc[mt][nt], a[mt][0], a[mt][1], a[mt][2], a[mt][3],
                            b[p][2 * q], b[p][2 * q + 1]);
                }
            }
        }

        int nx = it + NSTAGE - 1;
        if (nx < KT) {
            uint32_t sn = (nx % NSTAGE) * STAGE_BYTES;
            int k0 = nx * 32;
            cpasync16(dA0 + sn, Ag + k0);
            cpasync16(dA1 + sn, Ag + k0 + 8);
            cpasync16(dB0 + sn, Wg + k0);
            cpasync16(dB1 + sn, Wg + k0 + 8);
        }
        asm volatile("cp.async.commit_group;\n");
    }

    // epilogue
#pragma unroll
    for (int mt = 0; mt < 4; mt++) {
        int rr = m0 + wm + mt * 16 + g;
#pragma unroll
        for (int nt = 0; nt < 4; nt++) {
            int cc = n0 + wn + nt * 8 + 2 * t;
            float v0 = acc[mt][nt][0], v1 = acc[mt][nt][1];
            float v2 = acc[mt][nt][2], v3 = acc[mt][nt][3];
            if (BIAS) {
                float b0 = bias[cc], b1 = bias[cc + 1];
                v0 += b0; v1 += b1; v2 += b0; v3 += b1;
            }
            if (RES) {
                const float* rp0 = res + (size_t)rr * N + cc;
                const float* rp1 = res + (size_t)(rr + 8) * N + cc;
                v0 += rp0[0]; v1 += rp0[1];
                v2 += rp1[0]; v3 += rp1[1];
            }
            if (GELU) {
                v0 = gelu_tanh(v0); v1 = gelu_tanh(v1);
                v2 = gelu_tanh(v2); v3 = gelu_tanh(v3);
            }
            if (OUTH) {
                __half* C = (__half*)Cout;
                *(uint32_t*)(C + (size_t)rr * N + cc)       = packh2(v0, v1);
                *(uint32_t*)(C + (size_t)(rr + 8) * N + cc) = packh2(v2, v3);
            } else {
                float* C = (float*)Cout;
                *(float2*)(C + (size_t)rr * N + cc)       = make_float2(v0, v1);
                *(float2*)(C + (size_t)(rr + 8) * N + cc) = make_float2(v2, v3);
            }
        }
    }
}

// ---------------------------------------------------------------------------
// Tensor-core causal flash attention (tf32 compute, half I/O)
// ---------------------------------------------------------------------------
#define KST 68
#define VST 68
#define PST 68

extern __shared__ uint32_t s_attn[];

__global__ void __launch_bounds__(256) attn_tc_kernel()
{
    uint32_t* sK  = s_attn;
    uint32_t* sVT = s_attn + 64 * KST;
    uint32_t* sP  = s_attn + 64 * KST + 64 * VST;

    int tid = threadIdx.x;
    int bh = blockIdx.y;
    int b = bh >> 4, h = bh & 15;
    int qi = (int)(gridDim.x - 1) - (int)blockIdx.x;
    int q0 = qi * 128;

    int warp = tid >> 5, lane = tid & 31;
    int wm = warp * 16;
    int g = lane >> 2, t = lane & 3;

    int r0 = q0 + wm + g;
    int r1 = r0 + 8;
    int tok0 = b * SEQ + r0;

    const __half* Qb  = g_qh + (size_t)tok0 * DEMB + h * 64;
    const __half* Qb8 = Qb + (size_t)8 * DEMB;
    uint32_t qf[8][4];
#pragma unroll
    for (int kc = 0; kc < 8; kc++) {
        qf[kc][0] = f2tf(0.125f * __half2float(Qb [8 * kc + t]));
        qf[kc][1] = f2tf(0.125f * __half2float(Qb8[8 * kc + t]));
        qf[kc][2] = f2tf(0.125f * __half2float(Qb [8 * kc + t + 4]));
        qf[kc][3] = f2tf(0.125f * __half2float(Qb8[8 * kc + t + 4]));
    }

    float of[8][4];
#pragma unroll
    for (int j = 0; j < 8; j++)
#pragma unroll
        for (int c = 0; c < 4; c++) of[j][c] = 0.f;
    float m0 = -1e30f, m1 = -1e30f, l0 = 0.f, l1 = 0.f;

    int krow = tid >> 2;
    int kcg  = tid & 3;

    int ktmax = (q0 >> 6) + 1;
    for (int kt = 0; kt <= ktmax; kt++) {
        __syncthreads();
        {
            int ktok = b * SEQ + kt * 64 + krow;
            const uint4* Ksrc = (const uint4*)(g_kh + (size_t)ktok * DEMB + h * 64);
            const uint4* Vsrc = (const uint4*)(g_vh + (size_t)ktok * DEMB + h * 64);
            int pk = 8 * (krow & 7) + (krow >> 3);
#pragma unroll
            for (int j = 0; j < 2; j++) {
                int u4 = kcg * 2 + j;          // 0..7, 8 halves each
                int d0 = u4 * 8;
                uint4 kraw = Ksrc[u4];
                const __half2* kp = (const __half2*)&kraw;
                uint32_t* kr = sK + krow * KST + u4;
#pragma unroll
                for (int i = 0; i < 4; i++) {
                    float2 f = __half22float2(kp[i]);
                    kr[8 * (2 * i)]     = f2tf(f.x);
                    kr[8 * (2 * i + 1)] = f2tf(f.y);
                }
                uint4 vraw = Vsrc[u4];
                const __half2* vp = (const __half2*)&vraw;
#pragma unroll
                for (int i = 0; i < 4; i++) {
                    float2 f = __half22float2(vp[i]);
                    sVT[(d0 + 2 * i) * VST + pk]     = f2tf(f.x);
                    sVT[(d0 + 2 * i + 1) * VST + pk] = f2tf(f.y);
                }
            }
        }
        __syncthreads();

        float sf[8][4];
#pragma unroll
        for (int jn = 0; jn < 8; jn++) {
            const uint32_t* kr = sK + (8 * jn + g) * KST;
            uint4 bl0 = *(const uint4*)(kr + 8 * t);
            uint4 bl1 = *(const uint4*)(kr + 8 * t + 4);
            uint4 bh0 = *(const uint4*)(kr + 8 * (t + 4));
            uint4 bh1 = *(const uint4*)(kr + 8 * (t + 4) + 4);
            uint32_t b0w[8], b1w[8];
            u8from(b0w, bl0, bl1);
            u8from(b1w, bh0, bh1);
            float c[4] = {0.f, 0.f, 0.f, 0.f};
#pragma unroll
            for (int kc = 0; kc < 8; kc++)
                mma_tf32(c, qf[kc][0], qf[kc][1], qf[kc][2], qf[kc][3],
                         b0w[kc], b1w[kc]);
            sf[jn][0] = c[0]; sf[jn][1] = c[1];
            sf[jn][2] = c[2]; sf[jn][3] = c[3];
        }

        if (kt * 64 + 63 > q0 + wm) {
#pragma unroll
            for (int jn = 0; jn < 8; jn++) {
                int col = kt * 64 + 8 * jn + 2 * t;
                if (col     > r0) sf[jn][0] = -1e30f;
                if (col + 1 > r0) sf[jn][1] = -1e30f;
                if (col     > r1) sf[jn][2] = -1e30f;
                if (col + 1 > r1) sf[jn][3] = -1e30f;
            }
        }

        float rx0 = -1e30f, rx1 = -1e30f;
#pragma unroll
        for (int jn = 0; jn < 8; jn++) {
            rx0 = fmaxf(rx0, fmaxf(sf[jn][0], sf[jn][1]));
            rx1 = fmaxf(rx1, fmaxf(sf[jn][2], sf[jn][3]));
        }
        rx0 = fmaxf(rx0, __shfl_xor_sync(0xffffffffu, rx0, 1));
        rx0 = fmaxf(rx0, __shfl_xor_sync(0xffffffffu, rx0, 2));
        rx1 = fmaxf(rx1, __shfl_xor_sync(0xffffffffu, rx1, 1));
        rx1 = fmaxf(rx1, __shfl_xor_sync(0xffffffffu, rx1, 2));

        float mn0 = fmaxf(m0, rx0), mn1 = fmaxf(m1, rx1);
        float cor0 = __expf(m0 - mn0), cor1 = __expf(m1 - mn1);
        m0 = mn0; m1 = mn1;
        l0 *= cor0; l1 *= cor1;
#pragma unroll
        for (int j = 0; j < 8; j++) {
            of[j][0] *= cor0; of[j][1] *= cor0;
            of[j][2] *= cor1; of[j][3] *= cor1;
        }

        uint32_t* pw  = sP + (wm + g) * PST;
        uint32_t* pw8 = sP + (wm + 8 + g) * PST;
#pragma unroll
        for (int jn = 0; jn < 8; jn++) {
            float p0 = __expf(sf[jn][0] - m0);
            float p1 = __expf(sf[jn][1] - m0);
            float p2 = __expf(sf[jn][2] - m1);
            float p3 = __expf(sf[jn][3] - m1);
            l0 += p0 + p1; l1 += p2 + p3;
            pw [16 * t + jn]     = f2tf(p0);
            pw [16 * t + 8 + jn] = f2tf(p1);
            pw8[16 * t + jn]     = f2tf(p2);
            pw8[16 * t + 8 + jn] = f2tf(p3);
        }
        __syncwarp();

        const uint32_t* p0r = sP + (wm + g) * PST;
        const uint32_t* p8r = sP + (wm + 8 + g) * PST;
        uint4 A0a = *(const uint4*)(p0r + 8 * t);
        uint4 A0b = *(const uint4*)(p0r + 8 * t + 4);
        uint4 A2a = *(const uint4*)(p0r + 8 * (t + 4));
        uint4 A2b = *(const uint4*)(p0r + 8 * (t + 4) + 4);
        uint4 A1a = *(const uint4*)(p8r + 8 * t);
        uint4 A1b = *(const uint4*)(p8r + 8 * t + 4);
        uint4 A3a = *(const uint4*)(p8r + 8 * (t + 4));
        uint4 A3b = *(const uint4*)(p8r + 8 * (t + 4) + 4);
        uint32_t a0w[8], a1w[8], a2w[8], a3w[8];
        u8from(a0w, A0a, A0b);
        u8from(a1w, A1a, A1b);
        u8from(a2w, A2a, A2b);
        u8from(a3w, A3a, A3b);

#pragma unroll
        for (int jd = 0; jd < 8; jd++) {
            const uint32_t* vr = sVT + (8 * jd + g) * VST;
            uint4 vb0a = *(const uint4*)(vr + 8 * t);
            uint4 vb0b = *(const uint4*)(vr + 8 * t + 4);
            uint4 vb1a = *(const uint4*)(vr + 8 * (t + 4));
            uint4 vb1b = *(const uint4*)(vr + 8 * (t + 4) + 4);
            uint32_t b0w[8], b1w[8];
            u8from(b0w, vb0a, vb0b);
            u8from(b1w, vb1a, vb1b);
#pragma unroll
            for (int kc = 0; kc < 8; kc++)
                mma_tf32(of[jd], a0w[kc], a1w[kc], a2w[kc], a3w[kc],
                         b0w[kc], b1w[kc]);
        }
    }

    l0 += __shfl_xor_sync(0xffffffffu, l0, 1);
    l0 += __shfl_xor_sync(0xffffffffu, l0, 2);
    l1 += __shfl_xor_sync(0xffffffffu, l1, 1);
    l1 += __shfl_xor_sync(0xffffffffu, l1, 2);
    float i0 = 1.f / l0, i1 = 1.f / l1;

    __half* C0 = g_ctxh + (size_t)tok0 * DEMB + h * 64;
    __half* C1 = C0 + (size_t)8 * DEMB;
#pragma unroll
    for (int jd = 0; jd < 8; jd++) {
        *(uint32_t*)(C0 + 8 * jd + 2 * t) = packh2(of[jd][0] * i0, of[jd][1] * i0);
        *(uint32_t*)(C1 + 8 * jd + 2 * t) = packh2(of[jd][2] * i1, of[jd][3] * i1);
    }
}

#define ATTN_SMEM ((64 * KST + 64 * VST + 128 * PST) * 4)
#define GEMM_SMEM (2 * NSTAGE * STAGE_BYTES)

// ---------------------------------------------------------------------------
// Launch
// ---------------------------------------------------------------------------
extern "C" void kernel_launch(void* const* d_in, const int* in_sizes, int n_in,
                              void* d_out, int out_size)
{
    const float* x     = (const float*)d_in[0];
    const float* wq    = (const float*)d_in[1];
    const float* wk    = (const float*)d_in[2];
    const float* wv    = (const float*)d_in[3];
    const float* wo    = (const float*)d_in[4];
    const float* bo    = (const float*)d_in[5];
    const float* w1    = (const float*)d_in[6];
    const float* b1    = (const float*)d_in[7];
    const float* w2    = (const float*)d_in[8];
    const float* b2    = (const float*)d_in[9];
    const float* ln1_s = (const float*)d_in[10];
    const float* ln1_b = (const float*)d_in[11];
    const float* ln2_s = (const float*)d_in[12];
    const float* ln2_b = (const float*)d_in[13];
    float* out = (float*)d_out;

    __half *p_lnh, *p_qh, *p_kh, *p_vh, *p_ctxh, *p_ffh;
    __half *p_wqh, *p_wkh, *p_wvh, *p_woh, *p_w1h, *p_w2h;
    float *p_h;
    cudaGetSymbolAddress((void**)&p_lnh,  g_lnh);
    cudaGetSymbolAddress((void**)&p_qh,   g_qh);
    cudaGetSymbolAddress((void**)&p_kh,   g_kh);
    cudaGetSymbolAddress((void**)&p_vh,   g_vh);
    cudaGetSymbolAddress((void**)&p_ctxh, g_ctxh);
    cudaGetSymbolAddress((void**)&p_ffh,  g_ffh);
    cudaGetSymbolAddress((void**)&p_h,    g_h);
    cudaGetSymbolAddress((void**)&p_wqh,  g_wqh);
    cudaGetSymbolAddress((void**)&p_wkh,  g_wkh);
    cudaGetSymbolAddress((void**)&p_wvh,  g_wvh);
    cudaGetSymbolAddress((void**)&p_woh,  g_woh);
    cudaGetSymbolAddress((void**)&p_w1h,  g_w1h);
    cudaGetSymbolAddress((void**)&p_w2h,  g_w2h);

    cudaFuncSetAttribute(attn_tc_kernel,
        cudaFuncAttributeMaxDynamicSharedMemorySize, ATTN_SMEM);
    cudaFuncSetAttribute(gemm_h<0,0,0,1>,
        cudaFuncAttributeMaxDynamicSharedMemorySize, GEMM_SMEM);
    cudaFuncSetAttribute(gemm_h<1,0,1,0>,
        cudaFuncAttributeMaxDynamicSharedMemorySize, GEMM_SMEM);
    cudaFuncSetAttribute(gemm_h<1,1,0,1>,
        cudaFuncAttributeMaxDynamicSharedMemorySize, GEMM_SMEM);

    // weight conversion (runs every launch; deterministic)
    cvt_w<<<256, 256>>>(wq, p_wqh, DEMB * DEMB / 4);
    cvt_w<<<256, 256>>>(wk, p_wkh, DEMB * DEMB / 4);
    cvt_w<<<256, 256>>>(wv, p_wvh, DEMB * DEMB / 4);
    cvt_w<<<256, 256>>>(wo, p_woh, DEMB * DEMB / 4);
    cvt_w<<<512, 256>>>(w1, p_w1h, DFF * DEMB / 4);
    cvt_w<<<512, 256>>>(w2, p_w2h, DEMB * DFF / 4);

    dim3 gD(DEMB / 128, NTOK / 128);
    dim3 gF(DFF  / 128, NTOK / 128);

    ln_kernel<<<NTOK, 256>>>(x, ln1_s, ln1_b, p_lnh);
    gemm_h<0,0,0,1><<<gD, 256, GEMM_SMEM>>>(p_lnh, p_wqh, nullptr, nullptr, p_qh, NTOK, DEMB, DEMB);
    gemm_h<0,0,0,1><<<gD, 256, GEMM_SMEM>>>(p_lnh, p_wkh, nullptr, nullptr, p_kh, NTOK, DEMB, DEMB);
    gemm_h<0,0,0,1><<<gD, 256, GEMM_SMEM>>>(p_lnh, p_wvh, nullptr, nullptr, p_vh, NTOK, DEMB, DEMB);
    attn_tc_kernel<<<dim3(SEQ / 128, 2 * NH), 256, ATTN_SMEM>>>();
    gemm_h<1,0,1,0><<<gD, 256, GEMM_SMEM>>>(p_ctxh, p_woh, bo, x, p_h, NTOK, DEMB, DEMB);
    ln_kernel<<<NTOK, 256>>>(p_h, ln2_s, ln2_b, p_lnh);
    gemm_h<1,1,0,1><<<gF, 256, GEMM_SMEM>>>(p_lnh, p_w1h, b1, nullptr, p_ffh, NTOK, DFF, DEMB);
    gemm_h<1,0,1,0><<<gD, 256, GEMM_SMEM>>>(p_ffh, p_w2h, b2, p_h, out, NTOK, DEMB, DFF);
}